// round 5
// baseline (speedup 1.0000x reference)
#include <cuda_runtime.h>
#include <cstdint>

// BorderLoss: mean( w * BCEwithlogits(x, y) ), w = 1 + border(y),
// border = 3x3dilate(y) & ~3x3erode(y), RATIO=2.
// x: [64,512,512] f32, y: [64,512,512] i32 in {0,1}. Output: 1 float.
//
// Identities:
//   loss = softplus((1-2y)*x)          (exact rewrite; |x|<~6 so no overflow guard)
//   erode = 3x3 AND, dilate = 3x3 OR (binary mask); bytes packed as {0,0x80}
//   w=2 on border == +1 to loss exponent (loss >= softplus(-6) ~ 2.5e-3, always normal)
//   SAME padding == index clamp (idempotent duplicates under min/max)
//
// Round-2 layout: 8 px/lane (warp = 256 cols x 8 rows) -> 8192 warps for
// latency hiding. Interior column halo maintained by edge lanes via one
// predicated scalar y-load per row. Single kernel: last block reduces
// per-block partials and writes the scalar output.

static constexpr int W  = 512;
static constexpr int H  = 512;
static constexpr int NI = 64;
static constexpr int ROWS_PER_WARP = 8;
static constexpr int GRID = NI * (H / 16);   // block = 4 warps = 2 colhalves x 16 rows

__device__ float    g_part[GRID];
__device__ unsigned g_ticket = 0;

__global__ __launch_bounds__(128)
void border_loss_kernel(const float* __restrict__ x,
                        const int*   __restrict__ y,
                        float* __restrict__ out)
{
    const int img     = blockIdx.x >> 5;          // 32 row-blocks per image
    const int rowblk  = blockIdx.x & 31;
    const int warp    = threadIdx.x >> 5;
    const int lane    = threadIdx.x & 31;
    const int colhalf = warp & 1;
    const int row0    = rowblk * 16 + (warp >> 1) * 8;
    const int col0    = colhalf * 256 + lane * 8;  // 8 px per lane

    const size_t imgoff = (size_t)img * H * W;
    const float* xbase = x + imgoff + (size_t)row0 * W + col0;
    const int*   ybase = y + imgoff + col0;

    // Interior column-boundary halo: edge lane tracks the neighbor column.
    const bool edge  = (colhalf == 0) ? (lane == 31) : (lane == 0);
    const int  nbcol = (colhalf == 0) ? 256 : 255;
    const int* ynb   = y + imgoff + nbcol;

    // Packed mask rows: 2 regs x 4 bytes, byte value in {0, 0x80}
    unsigned pm[2], cm[2], nm[2];

    auto loadm = [&](int g, unsigned m[2]) {
        const int4* p = (const int4*)(ybase + (size_t)g * W);
#pragma unroll
        for (int j = 0; j < 2; j++) {
            int4 v = p[j];
            unsigned p01 = __byte_perm((unsigned)v.x, (unsigned)v.y, 0x0040);
            unsigned p23 = __byte_perm((unsigned)v.z, (unsigned)v.w, 0x0040);
            m[j] = __byte_perm(p01, p23, 0x5410) << 7;   // each byte: y<<7
        }
    };

    const int rtop = (row0 == 0) ? 0 : row0 - 1;
    loadm(rtop, pm);          // top clamp (idempotent for min/max)
    loadm(row0, cm);

    unsigned nb_p = 0, nb_c = 0;
    if (edge) {
        nb_p = ((unsigned)ynb[(size_t)rtop * W]) << 7;
        nb_c = ((unsigned)ynb[(size_t)row0 * W]) << 7;
    }

    float acc = 0.0f;

#pragma unroll
    for (int r = 0; r < ROWS_PER_WARP; r++) {
        const int g = row0 + r;
        const int gn = (g + 1 < H) ? g + 1 : g;    // bottom clamp
        loadm(gn, nm);

        unsigned nb_n = nb_c;
        if (edge) nb_n = ((unsigned)ynb[(size_t)gn * W]) << 7;

        // Vertical 3-tap: AND = min, OR = max
        unsigned vmn[2], vmx[2];
#pragma unroll
        for (int j = 0; j < 2; j++) {
            vmn[j] = pm[j] & cm[j] & nm[j];
            vmx[j] = pm[j] | cm[j] | nm[j];
        }
        const unsigned nbmn = nb_p & nb_c & nb_n;
        const unsigned nbmx = nb_p | nb_c | nb_n;
        const unsigned nb_pack = nbmn | (nbmx << 8);   // byte0=mn, byte1=mx

        // Cross-lane halo: pack (min,max) edge bytes, one shfl each direction.
        unsigned el = __byte_perm(vmn[0], vmx[0], 0x0040); // b0=mn.b0, b1=mx.b0
        unsigned eh = __byte_perm(vmn[1], vmx[1], 0x0073); // b0=mn.b3, b1=mx.b3
        unsigned fromL = __shfl_up_sync(0xffffffffu, eh, 1);
        unsigned fromR = __shfl_down_sync(0xffffffffu, el, 1);
        if (lane == 0)  fromL = (colhalf == 1) ? nb_pack : el;  // interior halo / img clamp
        if (lane == 31) fromR = (colhalf == 0) ? nb_pack : eh;

        unsigned border[2];
#pragma unroll
        for (int j = 0; j < 2; j++) {
            unsigned Lmn = (j == 0) ? __byte_perm(vmn[0], fromL, 0x2104)
                                    : __byte_perm(vmn[1], vmn[0], 0x2107);
            unsigned Lmx = (j == 0) ? __byte_perm(vmx[0], fromL, 0x2105)
                                    : __byte_perm(vmx[1], vmx[0], 0x2107);
            unsigned Rmn = (j == 1) ? __byte_perm(vmn[1], fromR, 0x4321)
                                    : __byte_perm(vmn[0], vmn[1], 0x4321);
            unsigned Rmx = (j == 1) ? __byte_perm(vmx[1], fromR, 0x5321)
                                    : __byte_perm(vmx[0], vmx[1], 0x4321);
            // border byte = dilate & ~erode, values in {0, 0x80}
            border[j] = (vmx[j] | Lmx | Rmx) & ~(vmn[j] & Lmn & Rmn);
        }

        // Loss + weight + accumulate
        const float4* xr = (const float4*)(xbase + (size_t)r * W);
#pragma unroll
        for (int j = 0; j < 2; j++) {
            float4 xv = xr[j];
            float xsv[4] = {xv.x, xv.y, xv.z, xv.w};
#pragma unroll
            for (int i = 0; i < 4; i++) {
                // sign: 0x80000000 iff y==1 (cm byte i == 0x80)
                unsigned sgn = __byte_perm(cm[j], 0u, 0x0444 | (i << 12));
                float z = __int_as_float(__float_as_int(xsv[i]) ^ sgn);
                float l = __logf(1.0f + __expf(z));     // softplus, z in [-6,6]
                // weight: +0x00800000 (exponent +1) iff border
                unsigned wb = __byte_perm(border[j], 0u, 0x4044 | (i << 8));
                acc += __int_as_float(__float_as_int(l) + wb);
            }
        }

        // rotate rows
#pragma unroll
        for (int j = 0; j < 2; j++) { pm[j] = cm[j]; cm[j] = nm[j]; }
        nb_p = nb_c; nb_c = nb_n;
    }

    // ---- block reduce ----
#pragma unroll
    for (int o = 16; o; o >>= 1)
        acc += __shfl_down_sync(0xffffffffu, acc, o);

    __shared__ float ws[4];
    __shared__ int s_last;
    if (lane == 0) ws[warp] = acc;
    __syncthreads();

    if (threadIdx.x == 0) {
        g_part[blockIdx.x] = (ws[0] + ws[1]) + (ws[2] + ws[3]);
        __threadfence();
        unsigned t = atomicAdd(&g_ticket, 1u);
        s_last = (t == (unsigned)(GRID - 1));
    }
    __syncthreads();

    // ---- last block: final deterministic reduction, write scalar ----
    if (s_last) {
        float v = 0.0f;
        for (int i = threadIdx.x; i < GRID; i += 128)
            v += __ldcg(&g_part[i]);
#pragma unroll
        for (int o = 16; o; o >>= 1)
            v += __shfl_down_sync(0xffffffffu, v, o);
        if (lane == 0) ws[warp] = v;
        __syncthreads();
        if (threadIdx.x == 0) {
            *out = ((ws[0] + ws[1]) + (ws[2] + ws[3])) * (1.0f / 16777216.0f);
            g_ticket = 0;   // reset for next graph replay
        }
    }
}

extern "C" void kernel_launch(void* const* d_in, const int* in_sizes, int n_in,
                              void* d_out, int out_size)
{
    const float* x = (const float*)d_in[0];
    const int*   y = (const int*)d_in[1];
    float* out = (float*)d_out;

    border_loss_kernel<<<GRID, 128>>>(x, y, out);
}

// round 7
// speedup vs baseline: 1.3019x; 1.3019x over previous
#include <cuda_runtime.h>
#include <cstdint>

// BorderLoss: mean( w * BCEwithlogits(x, y) ), w = 1 + border(y),
// border = 3x3dilate(y) & ~3x3erode(y), RATIO=2.
// x: [64,512,512] f32, y: [64,512,512] i32 in {0,1}. Output: 1 float.
//
// Identities:
//   loss = softplus((1-2y)*x)        (exact; |x|<~6 so no overflow guard needed)
//   erode = 3x3 AND, dilate = 3x3 OR (binary mask); bytes packed as {0,0x80}
//   w=2 on border == +1 to loss exponent (loss >= softplus(-6) ~ 2.5e-3, normal)
//   SAME padding == index clamp (idempotent duplicates under min/max)
//
// Geometry (round-1 winner): 16 px/lane, warp = full 512-col row x 8 rows.
// Deep per-warp MLP (4 int4 + 4 float4 independent loads per row) is what
// saturates HBM; occupancy is grid-limited and that is fine.
// Single kernel: per-block partials + ticket, last block writes the scalar.

static constexpr int W  = 512;
static constexpr int H  = 512;
static constexpr int NI = 64;
static constexpr int ROWS_PER_WARP = 8;      // block = 4 warps -> 32 rows
static constexpr int GRID = NI * (H / 32);   // 1024

__device__ float    g_part[GRID];
__device__ unsigned g_ticket = 0;

__global__ __launch_bounds__(128)
void border_loss_kernel(const float* __restrict__ x,
                        const int*   __restrict__ y,
                        float* __restrict__ out)
{
    const int img   = blockIdx.x >> 4;     // 16 strips per image
    const int strip = blockIdx.x & 15;
    const int warp  = threadIdx.x >> 5;
    const int lane  = threadIdx.x & 31;
    const int row0  = strip * 32 + warp * ROWS_PER_WARP;
    const int col0  = lane * 16;           // 16 px/lane, 32 lanes = 512 cols

    const size_t imgoff = (size_t)img * H * W;
    const float* xbase = x + imgoff + (size_t)row0 * W + col0;
    const int*   ybase = y + imgoff + col0;

    // Packed mask rows: 4 regs x 4 bytes, byte value in {0, 0x80}
    unsigned pm[4], cm[4], nm[4];

    auto loadm = [&](int g, unsigned m[4]) {
        const int4* p = (const int4*)(ybase + (size_t)g * W);
#pragma unroll
        for (int j = 0; j < 4; j++) {
            int4 v = __ldg(p + j);
            unsigned p01 = __byte_perm((unsigned)v.x, (unsigned)v.y, 0x0040);
            unsigned p23 = __byte_perm((unsigned)v.z, (unsigned)v.w, 0x0040);
            m[j] = __byte_perm(p01, p23, 0x5410) << 7;   // each byte: y<<7
        }
    };

    loadm(row0 == 0 ? 0 : row0 - 1, pm);   // top clamp (idempotent for min/max)
    loadm(row0, cm);

    float acc = 0.0f;

#pragma unroll
    for (int r = 0; r < ROWS_PER_WARP; r++) {
        const int g = row0 + r;
        if (g + 1 < H) {
            loadm(g + 1, nm);
        } else {
#pragma unroll
            for (int j = 0; j < 4; j++) nm[j] = cm[j];   // bottom clamp
        }

        // Vertical 3-tap: AND = min, OR = max (bytes in {0,0x80})
        unsigned vmn[4], vmx[4];
#pragma unroll
        for (int j = 0; j < 4; j++) {
            vmn[j] = pm[j] & cm[j] & nm[j];
            vmx[j] = pm[j] | cm[j] | nm[j];
        }

        // Cross-lane halo: pack (min,max) edge bytes, one shfl each direction.
        unsigned el = __byte_perm(vmn[0], vmx[0], 0x0040); // b0=mn.b0, b1=mx.b0
        unsigned eh = __byte_perm(vmn[3], vmx[3], 0x0073); // b0=mn.b3, b1=mx.b3
        unsigned fromL = __shfl_up_sync(0xffffffffu, eh, 1);
        unsigned fromR = __shfl_down_sync(0xffffffffu, el, 1);
        if (lane == 0)  fromL = el;   // col clamp: duplicate own col 0
        if (lane == 31) fromR = eh;   // col clamp: duplicate own col 511

        unsigned border[4];
#pragma unroll
        for (int j = 0; j < 4; j++) {
            unsigned Lmn = (j == 0) ? __byte_perm(vmn[0], fromL, 0x2104)
                                    : __byte_perm(vmn[j], vmn[j-1], 0x2107);
            unsigned Lmx = (j == 0) ? __byte_perm(vmx[0], fromL, 0x2105)
                                    : __byte_perm(vmx[j], vmx[j-1], 0x2107);
            unsigned Rmn = (j == 3) ? __byte_perm(vmn[3], fromR, 0x4321)
                                    : __byte_perm(vmn[j], vmn[j+1], 0x4321);
            unsigned Rmx = (j == 3) ? __byte_perm(vmx[3], fromR, 0x5321)
                                    : __byte_perm(vmx[j], vmx[j+1], 0x4321);
            // border byte = dilate & ~erode, values in {0, 0x80}
            border[j] = (vmx[j] | Lmx | Rmx) & ~(vmn[j] & Lmn & Rmn);
        }

        // Loss + weight + accumulate. x is read-once: stream (evict-first)
        // so L2 capacity stays available for y vertical-halo re-reads.
        const float4* xr = (const float4*)(xbase + (size_t)r * W);
#pragma unroll
        for (int j = 0; j < 4; j++) {
            float4 xv = __ldcs(xr + j);
            float xsv[4] = {xv.x, xv.y, xv.z, xv.w};
#pragma unroll
            for (int i = 0; i < 4; i++) {
                // sign: 0x80000000 iff y==1 (cm byte i == 0x80)
                unsigned sgn = __byte_perm(cm[j], 0u, 0x0444 | (i << 12));
                float z = __int_as_float(__float_as_int(xsv[i]) ^ sgn);
                float l = __logf(1.0f + __expf(z));     // softplus, z in [-6,6]
                // weight: +0x00800000 (exponent +1) iff border
                unsigned wb = __byte_perm(border[j], 0u, 0x4044 | (i << 8));
                acc += __int_as_float(__float_as_int(l) + wb);
            }
        }

        // rotate rows
#pragma unroll
        for (int j = 0; j < 4; j++) { pm[j] = cm[j]; cm[j] = nm[j]; }
    }

    // ---- block reduce ----
#pragma unroll
    for (int o = 16; o; o >>= 1)
        acc += __shfl_down_sync(0xffffffffu, acc, o);

    __shared__ float ws[4];
    __shared__ int s_last;
    if (lane == 0) ws[warp] = acc;
    __syncthreads();

    if (threadIdx.x == 0) {
        g_part[blockIdx.x] = (ws[0] + ws[1]) + (ws[2] + ws[3]);
        __threadfence();
        unsigned t = atomicAdd(&g_ticket, 1u);
        s_last = (t == (unsigned)(GRID - 1));
    }
    __syncthreads();

    // ---- last block: final deterministic reduction, write scalar ----
    if (s_last) {
        float v = 0.0f;
        for (int i = threadIdx.x; i < GRID; i += 128)
            v += __ldcg(&g_part[i]);
#pragma unroll
        for (int o = 16; o; o >>= 1)
            v += __shfl_down_sync(0xffffffffu, v, o);
        if (lane == 0) ws[warp] = v;
        __syncthreads();
        if (threadIdx.x == 0) {
            *out = ((ws[0] + ws[1]) + (ws[2] + ws[3])) * (1.0f / 16777216.0f);
            g_ticket = 0;   // reset for next graph replay
        }
    }
}

extern "C" void kernel_launch(void* const* d_in, const int* in_sizes, int n_in,
                              void* d_out, int out_size)
{
    const float* x = (const float*)d_in[0];
    const int*   y = (const int*)d_in[1];
    float* out = (float*)d_out;

    border_loss_kernel<<<GRID, 128>>>(x, y, out);
}